// round 16
// baseline (speedup 1.0000x reference)
#include <cuda_runtime.h>
#include <cuda_bf16.h>
#include <cuda_fp8.h>
#include <math.h>
#include <stdint.h>

#define BATCH 1024
#define FEAT  2048
#define NCLS  11003
#define NPAD  11008
#define NT1   172           // N tiles of 64 for gemm1
#define NCH   344           // 32-col LSE chunks (NPAD/32)
#define ROWS2 2048          // stacked [v; t]

#define ASCALE 64.0f
#define WSCALE 4.0f
#define DESCALE2 (1.0f / (ASCALE * ASCALE))   // gemm2 sim descale
#define LSE_MAX 28.0f                         // |logit| <= 28 always

#define WT_BLOCKS (344 * 16)            // wtrans sub-grid
#define G1F_BLOCKS 2536                 // full gemm1 tiles (mtile*172+ntile < 2536)
#define G2_BLOCKS  128                  // gemm2 128x64 tiles (8 m x 16 n)
#define HALF_BLOCKS 432                 // 216 split gemm1 tiles x 2 halves
#define TOT_BLOCKS (G1F_BLOCKS + G2_BLOCKS + HALF_BLOCKS)   // 3096

// ---------------- device scratch (static, no runtime alloc) ----------------
__device__ __align__(128) uint8_t g_a8[(size_t)ROWS2 * FEAT];   // fp8 [v-hat;t-hat] * 64
__device__ __align__(128) uint8_t g_w8t[(size_t)NPAD * FEAT];   // fp8 W^T [n][k] * 4
__device__ float g_colsqp[16 * NPAD];
__device__ float g_ll[ROWS2];
__device__ float g_psum[NCH * ROWS2];   // chunkwise sum exp(v - 28)
__device__ float g_gal_part[G2_BLOCKS];
__device__ float g_inst_part[32];
__device__ int   g_lab[BATCH];
__device__ int   g_ctr;                 // zero-init; self-resetting ticket

__device__ __forceinline__ uint8_t to_e4m3(float x) {
    __nv_fp8_e4m3 v(x);
    return *reinterpret_cast<uint8_t*>(&v);
}

// ======================= prep_fused: wtrans + normalize =======================
__global__ void prep_fused_kernel(const float* __restrict__ W,
                                  const float* __restrict__ vis,
                                  const float* __restrict__ txt,
                                  const int* __restrict__ lb) {
    __shared__ float s[128][33];
    __shared__ float sq[8][33];
    int bid = blockIdx.x;
    int t = threadIdx.x;

    if (bid < WT_BLOCKS) {
        // ---- wtrans: W -> fp8 [n][k] + colsq partials ----
        int tx = t & 31, ty = t >> 5;
        int c0 = (bid % 344) * 32, k0 = (bid / 344) * 128;
        int c = c0 + tx;
        float p = 0.f;
        #pragma unroll
        for (int i = 0; i < 16; i++) {
            int k = k0 + ty + 8 * i;
            float w = (c < NCLS) ? W[(size_t)k * NCLS + c] : 0.f;
            s[ty + 8 * i][tx] = w;
            p += w * w;
        }
        sq[ty][tx] = p;
        __syncthreads();
        if (ty == 0) {
            float ssum = 0.f;
            #pragma unroll
            for (int i = 0; i < 8; i++) ssum += sq[i][tx];
            g_colsqp[(bid / 344) * NPAD + c] = ssum;
        }
        #pragma unroll
        for (int j = 0; j < 4; j++) {
            int nl = ty + 8 * j;
            int kq = tx;
            uchar4 pk = make_uchar4(to_e4m3(s[4*kq+0][nl] * WSCALE),
                                    to_e4m3(s[4*kq+1][nl] * WSCALE),
                                    to_e4m3(s[4*kq+2][nl] * WSCALE),
                                    to_e4m3(s[4*kq+3][nl] * WSCALE));
            *(uint32_t*)(g_w8t + (size_t)(c0 + nl) * FEAT + k0 + 4 * kq) =
                *reinterpret_cast<uint32_t*>(&pk);
        }
    } else {
        // ---- normalize row r -> fp8; block WT_BLOCKS also loads labels ----
        int r = bid - WT_BLOCKS;        // 0..2047
        if (r == 0) {
            bool is64 = true;
            #pragma unroll
            for (int j = 1; j < 64; j += 2)
                if (lb[j] != 0) is64 = false;
            #pragma unroll
            for (int i = 0; i < 4; i++) {
                int idx = t + 256 * i;
                g_lab[idx] = is64 ? lb[2 * idx] : lb[idx];
            }
        }
        const float* src = (r < BATCH) ? (vis + (size_t)r * FEAT)
                                       : (txt + (size_t)(r - BATCH) * FEAT);
        float4 x0 = ((const float4*)src)[t];
        float4 x1 = ((const float4*)src)[t + 256];
        float ss = x0.x*x0.x + x0.y*x0.y + x0.z*x0.z + x0.w*x0.w
                 + x1.x*x1.x + x1.y*x1.y + x1.z*x1.z + x1.w*x1.w;
        #pragma unroll
        for (int o = 16; o > 0; o >>= 1) ss += __shfl_xor_sync(0xffffffffu, ss, o);
        float* ws = &sq[0][0];
        if ((t & 31) == 0) ws[t >> 5] = ss;
        __syncthreads();
        if (t == 0) {
            float sum = 0.f;
            #pragma unroll
            for (int i = 0; i < 8; i++) sum += ws[i];
            ws[8] = rsqrtf(sum);
        }
        __syncthreads();
        float fa = ws[8] * ASCALE;
        uchar4 p0 = make_uchar4(to_e4m3(x0.x*fa), to_e4m3(x0.y*fa),
                                to_e4m3(x0.z*fa), to_e4m3(x0.w*fa));
        uchar4 p1 = make_uchar4(to_e4m3(x1.x*fa), to_e4m3(x1.y*fa),
                                to_e4m3(x1.z*fa), to_e4m3(x1.w*fa));
        uint32_t* d8 = (uint32_t*)(g_a8 + (size_t)r * FEAT);
        d8[t]       = *reinterpret_cast<uint32_t*>(&p0);
        d8[t + 256] = *reinterpret_cast<uint32_t*>(&p1);
    }
}

// ---------------- mma helpers ----------------
__device__ __forceinline__ void ldmx4(uint32_t* r, uint32_t a) {
    asm volatile("ldmatrix.sync.aligned.m8n8.x4.shared.b16 {%0,%1,%2,%3},[%4];\n"
                 : "=r"(r[0]), "=r"(r[1]), "=r"(r[2]), "=r"(r[3]) : "r"(a));
}
__device__ __forceinline__ void mma16832f8(float* c, const uint32_t* a, const uint32_t* b) {
    asm volatile("mma.sync.aligned.m16n8k32.row.col.f32.e4m3.e4m3.f32 "
                 "{%0,%1,%2,%3},{%4,%5,%6,%7},{%8,%9},{%0,%1,%2,%3};\n"
                 : "+f"(c[0]), "+f"(c[1]), "+f"(c[2]), "+f"(c[3])
                 : "r"(a[0]), "r"(a[1]), "r"(a[2]), "r"(a[3]),
                   "r"(b[0]), "r"(b[1]));
}
__device__ __forceinline__ void cpa16(uint32_t dst, const void* src) {
    asm volatile("cp.async.cg.shared.global [%0], [%1], 16;" :: "r"(dst), "l"(src));
}
__device__ __forceinline__ void cpa_commit() {
    asm volatile("cp.async.commit_group;" ::: "memory");
}
template <int N> __device__ __forceinline__ void cpa_wait() {
    asm volatile("cp.async.wait_group %0;" :: "n"(N) : "memory");
}

// ======================= shared fp8 (MF*64)x64x2048 mainloop =======================
// MF=2: 128-row tile (full). MF=1: 64-row tile (half-duration tail filler).
// De-convoy edits: per-warp ks rotation (cols precomputed in rotated order) and
// cp.async issue deferred until after the first ks group (mma shadows LDGSTS).
#define F8_BB   8192
#define G1_SMEM (3 * (128 * 128 + F8_BB))   // 73728 (worst case MF=2)
#define G1_NSTG 16

template <int MF>
__device__ __forceinline__ void fp8_mainloop(
    const uint8_t* __restrict__ asrc_base, const uint8_t* __restrict__ bsrc_base,
    uint32_t sb, int tid, int lane, int warp, int wm, int wn,
    float* sInv, int inv_base, float c[2][4][4])
{
    constexpr int AB  = MF * 64 * 128;
    constexpr int STG = AB + F8_BB;

    #pragma unroll
    for (int mf = 0; mf < MF; mf++)
        #pragma unroll
        for (int nf = 0; nf < 4; nf++)
            #pragma unroll
            for (int j = 0; j < 4; j++) c[mf][nf][j] = 0.f;

    int arow = tid >> 3, q = tid & 7;
    uint32_t asw = (uint32_t)((q ^ (arow & 7)) << 4);
    uint32_t adst0 = (uint32_t)(arow * 128) + asw;
    const uint8_t* asrc0 = asrc_base + (size_t)arow * FEAT + q * 16;
    uint32_t bdst0 = (uint32_t)AB + (uint32_t)(arow * 128) + asw;
    const uint8_t* bsrc0 = bsrc_base + (size_t)arow * FEAT + q * 16;

    int koff = 0;
    auto issue_stage = [&](uint32_t bufbase) {
        #pragma unroll
        for (int i = 0; i < 2 * MF; i++)
            cpa16(bufbase + adst0 + i * 4096, asrc0 + (size_t)i * 32 * FEAT + koff);
        #pragma unroll
        for (int i = 0; i < 2; i++)
            cpa16(bufbase + bdst0 + i * 4096, bsrc0 + (size_t)i * 32 * FEAT + koff);
        cpa_commit();
        koff += 128;
    };

    int arow0 = wm * (16 * MF) + (lane & 15);
    int brow0 = wn * 32 + (lane & 7) + ((lane >> 4) << 3);
    int ahi = lane >> 4, bhi = (lane >> 3) & 1;
    uint32_t aoff = (uint32_t)(arow0 * 128);
    uint32_t boff = (uint32_t)AB + (uint32_t)(brow0 * 128);
    // per-warp rotated ks order: slot ksi holds offsets for ks = (ksi+warp)&3
    uint32_t colA[4], colB[4];
    #pragma unroll
    for (int ksi = 0; ksi < 4; ksi++) {
        int ks = (ksi + warp) & 3;
        colA[ksi] = (uint32_t)(((ks * 2 + ahi) ^ (arow0 & 7)) << 4);
        colB[ksi] = (uint32_t)(((ks * 2 + bhi) ^ (brow0 & 7)) << 4);
    }

    issue_stage(sb);
    issue_stage(sb + STG);

    if (inv_base >= 0 && tid < 64) {     // hidden under pipeline fill
        int cidx = inv_base + tid;
        float s = 0.f;
        #pragma unroll
        for (int i = 0; i < 16; i++) s += g_colsqp[i * NPAD + cidx];
        sInv[tid] = (cidx < NCLS) ? (28.0f / (ASCALE * WSCALE)) * rsqrtf(s) : 0.f;
    }

    for (int kt = 0; kt < G1_NSTG; kt++) {
        uint32_t bufbase = sb + (kt % 3) * STG;
        if (kt < G1_NSTG - 1) cpa_wait<1>(); else cpa_wait<0>();
        __syncthreads();

        uint32_t abase = bufbase + aoff;
        uint32_t bbase = bufbase + boff;

        auto do_ks = [&](int ksi) {
            uint32_t a[2][4], b[4][2];
            #pragma unroll
            for (int mf = 0; mf < MF; mf++)
                ldmx4(a[mf], abase + mf * 2048 + colA[ksi]);
            {
                uint32_t r[4];
                ldmx4(r, bbase + colB[ksi]);
                b[0][0] = r[0]; b[0][1] = r[1];
                b[1][0] = r[2]; b[1][1] = r[3];
                ldmx4(r, bbase + 2048 + colB[ksi]);
                b[2][0] = r[0]; b[2][1] = r[1];
                b[3][0] = r[2]; b[3][1] = r[3];
            }
            #pragma unroll
            for (int mf = 0; mf < MF; mf++)
                #pragma unroll
                for (int nf = 0; nf < 4; nf++)
                    mma16832f8(c[mf][nf], a[mf], b[nf]);
        };

        do_ks(0);
        if (kt + 2 < G1_NSTG) issue_stage(sb + ((kt + 2) % 3) * STG);
        do_ks(1);
        do_ks(2);
        do_ks(3);
    }
}

// gemm1 epilogue: fixed-max (28) chunkwise sum-exp
template <int MF>
__device__ __forceinline__ void g1_epilogue(int rowbase, int ntile,
                                            float c[2][4][4], const float* sInv,
                                            int lane, int wm, int wn)
{
    int g = lane >> 2, tg = lane & 3;
    #pragma unroll
    for (int mf = 0; mf < MF; mf++)
        #pragma unroll
        for (int pr = 0; pr < 2; pr++) {
            int R = rowbase + wm * (16 * MF) + mf * 16 + pr * 8 + g;
            int lbl = g_lab[R & (BATCH - 1)];
            float s = 0.f;
            #pragma unroll
            for (int nf = 0; nf < 4; nf++)
                #pragma unroll
                for (int j = 0; j < 2; j++) {
                    int nl = wn * 32 + nf * 8 + tg * 2 + j;
                    int n = ntile * 64 + nl;
                    float val = c[mf][nf][pr * 2 + j] * sInv[nl];
                    if (n >= NCLS) val = -1e30f;
                    if (n == lbl) g_ll[R] = val;
                    s += __expf(val - LSE_MAX);
                }
            s += __shfl_xor_sync(0xffffffffu, s, 1);
            s += __shfl_xor_sync(0xffffffffu, s, 2);
            if (tg == 0) {
                int chunk = ntile * 2 + wn;
                g_psum[chunk * ROWS2 + R] = s;
            }
        }
}

// ======================= gemm_fused =======================
// [0, 2536): gemm1 full 128-row tiles   (6 clean waves with gemm2: 2664 = 6*444)
// [2536, 2664): gemm2 128x64 tiles      (same duration as gemm1 fulls)
// [2664, 3096): gemm1 half 64-row tiles (T/2 duration -> packs the tail wave)
__global__ __launch_bounds__(256, 3) void gemm_fused_kernel() {
    extern __shared__ char smem[];
    __shared__ float sInv[64];
    int tid = threadIdx.x, warp = tid >> 5, lane = tid & 31;
    int wm = warp & 3, wn = warp >> 2;
    uint32_t sb = (uint32_t)__cvta_generic_to_shared(smem);
    float c[2][4][4];
    int bid = blockIdx.x;

    if (bid < G1F_BLOCKS) {
        // ---- gemm1 full tile ----
        int mtile = bid / NT1, ntile = bid % NT1;
        fp8_mainloop<2>(g_a8 + (size_t)(mtile * 128) * FEAT,
                        g_w8t + (size_t)(ntile * 64) * FEAT,
                        sb, tid, lane, warp, wm, wn, sInv, ntile * 64, c);
        g1_epilogue<2>(mtile * 128, ntile, c, sInv, lane, wm, wn);
    } else if (bid < G1F_BLOCKS + G2_BLOCKS) {
        // ---- gemm2: fp8 sim + soft-margin ----
        int bid2 = bid - G1F_BLOCKS;            // 0..127
        int ntile2 = bid2 & 15, mtile2 = bid2 >> 4;   // 16 n x 8 m
        fp8_mainloop<2>(g_a8 + (size_t)(mtile2 * 128) * FEAT,
                        g_a8 + (size_t)(BATCH + ntile2 * 64) * FEAT,
                        sb, tid, lane, warp, wm, wn, sInv, -1, c);

        int g = lane >> 2, tg = lane & 3;
        float local = 0.f;
        #pragma unroll
        for (int mf = 0; mf < 2; mf++)
            #pragma unroll
            for (int pr = 0; pr < 2; pr++) {
                int R = mtile2 * 128 + wm * 32 + mf * 16 + pr * 8 + g;
                int lr = g_lab[R];
                #pragma unroll
                for (int nf = 0; nf < 4; nf++)
                    #pragma unroll
                    for (int j = 0; j < 2; j++) {
                        int n = ntile2 * 64 + wn * 32 + nf * 8 + tg * 2 + j;
                        int lc = g_lab[n];
                        float s = c[mf][nf][pr * 2 + j] * DESCALE2;
                        float x = (lr == lc) ? (-10.f * (s - 0.6f))
                                             : (40.f * (s - 0.4f));
                        local += (x > 15.f) ? x : log1pf(__expf(x));
                    }
            }
        #pragma unroll
        for (int o = 16; o > 0; o >>= 1) local += __shfl_xor_sync(0xffffffffu, local, o);
        if (lane == 0) sInv[warp] = local;      // reuse sInv as scratch
        __syncthreads();
        if (tid == 0) {
            float t2 = 0.f;
            #pragma unroll
            for (int i = 0; i < 8; i++) t2 += sInv[i];
            g_gal_part[bid2] = t2;
        }
    } else {
        // ---- gemm1 half tile (64 rows) ----
        int h = bid - (G1F_BLOCKS + G2_BLOCKS);       // 0..431
        int gt = G1F_BLOCKS + (h >> 1);               // global tile 2536..2751
        int mtile = gt / NT1, ntile = gt % NT1;
        int half = h & 1;
        fp8_mainloop<1>(g_a8 + (size_t)(mtile * 128 + half * 64) * FEAT,
                        g_w8t + (size_t)(ntile * 64) * FEAT,
                        sb, tid, lane, warp, wm, wn, sInv, ntile * 64, c);
        g1_epilogue<1>(mtile * 128 + half * 64, ntile, c, sInv, lane, wm, wn);
    }
}

// ---------------- combine + finalize (fixed-max LSE; last-block pattern) ----------------
__global__ void combine_final_kernel(float* __restrict__ out) {
    int r = blockIdx.x * 64 + threadIdx.x;
    float s = 0.f;
    #pragma unroll 8
    for (int i = 0; i < NCH; i++) s += g_psum[i * ROWS2 + r];
    float contrib = LSE_MAX + logf(s) - g_ll[r];

    int lane = threadIdx.x & 31, wid = threadIdx.x >> 5;
    #pragma unroll
    for (int o = 16; o > 0; o >>= 1) contrib += __shfl_xor_sync(0xffffffffu, contrib, o);
    __shared__ float ws[2];
    __shared__ int s_ticket;
    if (lane == 0) ws[wid] = contrib;
    __syncthreads();
    if (threadIdx.x == 0) {
        g_inst_part[blockIdx.x] = ws[0] + ws[1];
        __threadfence();
        s_ticket = atomicAdd(&g_ctr, 1);
    }
    __syncthreads();
    if (s_ticket == 31) {
        if (threadIdx.x == 0) {
            float si = 0.f;
            for (int i = 0; i < 32; i++) si += g_inst_part[i];
            float sg = 0.f;
            for (int i = 0; i < G2_BLOCKS; i++) sg += g_gal_part[i];
            out[0] = si * (1.0f / BATCH);
            out[1] = 2.0f * sg / BATCH;
            g_ctr = 0;                   // reset for next graph replay
        }
    }
}

// ---------------- launch: 3 kernels, one stream ----------------
extern "C" void kernel_launch(void* const* d_in, const int* in_sizes, int n_in,
                              void* d_out, int out_size) {
    const float* vis = (const float*)d_in[0];
    const float* txt = (const float*)d_in[1];
    const int* lab = (const int*)d_in[2];
    const float* W = (const float*)d_in[3];
    float* out = (float*)d_out;

    cudaFuncSetAttribute(gemm_fused_kernel,
                         cudaFuncAttributeMaxDynamicSharedMemorySize, G1_SMEM);

    prep_fused_kernel<<<WT_BLOCKS + ROWS2, 256>>>(W, vis, txt, lab);
    gemm_fused_kernel<<<TOT_BLOCKS, 256, G1_SMEM>>>();
    combine_final_kernel<<<32, 64>>>(out);
}

// round 17
// speedup vs baseline: 1.0310x; 1.0310x over previous
#include <cuda_runtime.h>
#include <cuda_bf16.h>
#include <cuda_fp8.h>
#include <math.h>
#include <stdint.h>

#define BATCH 1024
#define FEAT  2048
#define NCLS  11003
#define NPAD  11008
#define NT1   172           // N tiles of 64 for gemm1
#define NCH   344           // 32-col LSE chunks (NPAD/32)
#define ROWS2 2048          // stacked [v; t]

#define ASCALE 64.0f
#define WSCALE 4.0f
#define DESCALE2 (1.0f / (ASCALE * ASCALE))   // gemm2 sim descale
#define LSE_MAX 28.0f                         // |logit| <= 28 always

#define WT_BLOCKS (344 * 16)            // wtrans sub-grid
#define G1F_BLOCKS 2536                 // full gemm1 tiles (mtile*172+ntile < 2536)
#define G2_BLOCKS  128                  // gemm2 128x64 tiles (8 m x 16 n)
#define HALF_BLOCKS 432                 // 216 split gemm1 tiles x 2 halves
#define TOT_BLOCKS (G1F_BLOCKS + G2_BLOCKS + HALF_BLOCKS)   // 3096

// ---------------- device scratch (static, no runtime alloc) ----------------
__device__ __align__(128) uint8_t g_a8[(size_t)ROWS2 * FEAT];   // fp8 [v-hat;t-hat] * 64
__device__ __align__(128) uint8_t g_w8t[(size_t)NPAD * FEAT];   // fp8 W^T [n][k] * 4
__device__ float g_colsqp[16 * NPAD];
__device__ float g_ll[ROWS2];
__device__ float g_psum[NCH * ROWS2];   // chunkwise sum exp(v - 28)
__device__ float g_gal_part[G2_BLOCKS];
__device__ float g_inst_part[32];
__device__ int   g_lab[BATCH];
__device__ int   g_ctr;                 // zero-init; self-resetting ticket

__device__ __forceinline__ uint8_t to_e4m3(float x) {
    __nv_fp8_e4m3 v(x);
    return *reinterpret_cast<uint8_t*>(&v);
}

// ======================= prep_fused: wtrans + normalize =======================
// wtrans staging uses a k-dependent XOR swizzle: element (k,c) lives at
// s[k][c ^ (k>>2)]. Stores (lanes vary c) and reads (k = 4*kq+i, lanes vary
// kq -> column nl^kq) are BOTH conflict-free; the old 33-pad layout had a
// 4-way conflict on every transpose read.
__global__ void prep_fused_kernel(const float* __restrict__ W,
                                  const float* __restrict__ vis,
                                  const float* __restrict__ txt,
                                  const int* __restrict__ lb) {
    __shared__ float s[128][32];
    __shared__ float sq[8][33];
    int bid = blockIdx.x;
    int t = threadIdx.x;

    if (bid < WT_BLOCKS) {
        // ---- wtrans: W -> fp8 [n][k] + colsq partials ----
        int tx = t & 31, ty = t >> 5;
        int c0 = (bid % 344) * 32, k0 = (bid / 344) * 128;
        int c = c0 + tx;
        float p = 0.f;
        #pragma unroll
        for (int i = 0; i < 16; i++) {
            int kk = ty + 8 * i;              // local k 0..127
            float w = (c < NCLS) ? W[(size_t)(k0 + kk) * NCLS + c] : 0.f;
            s[kk][tx ^ ((kk >> 2) & 31)] = w;
            p += w * w;
        }
        sq[ty][tx] = p;
        __syncthreads();
        if (ty == 0) {
            float ssum = 0.f;
            #pragma unroll
            for (int i = 0; i < 8; i++) ssum += sq[i][tx];
            g_colsqp[(bid / 344) * NPAD + c] = ssum;
        }
        #pragma unroll
        for (int j = 0; j < 4; j++) {
            int nl = ty + 8 * j;
            int kq = tx;
            int sc = nl ^ kq;                 // swizzled column for k = 4*kq+i
            uchar4 pk = make_uchar4(to_e4m3(s[4*kq+0][sc] * WSCALE),
                                    to_e4m3(s[4*kq+1][sc] * WSCALE),
                                    to_e4m3(s[4*kq+2][sc] * WSCALE),
                                    to_e4m3(s[4*kq+3][sc] * WSCALE));
            *(uint32_t*)(g_w8t + (size_t)(c0 + nl) * FEAT + k0 + 4 * kq) =
                *reinterpret_cast<uint32_t*>(&pk);
        }
    } else {
        // ---- normalize row r -> fp8; block WT_BLOCKS also loads labels ----
        int r = bid - WT_BLOCKS;        // 0..2047
        if (r == 0) {
            bool is64 = true;
            #pragma unroll
            for (int j = 1; j < 64; j += 2)
                if (lb[j] != 0) is64 = false;
            #pragma unroll
            for (int i = 0; i < 4; i++) {
                int idx = t + 256 * i;
                g_lab[idx] = is64 ? lb[2 * idx] : lb[idx];
            }
        }
        const float* src = (r < BATCH) ? (vis + (size_t)r * FEAT)
                                       : (txt + (size_t)(r - BATCH) * FEAT);
        float4 x0 = ((const float4*)src)[t];
        float4 x1 = ((const float4*)src)[t + 256];
        float ss = x0.x*x0.x + x0.y*x0.y + x0.z*x0.z + x0.w*x0.w
                 + x1.x*x1.x + x1.y*x1.y + x1.z*x1.z + x1.w*x1.w;
        #pragma unroll
        for (int o = 16; o > 0; o >>= 1) ss += __shfl_xor_sync(0xffffffffu, ss, o);
        float* ws = &sq[0][0];
        if ((t & 31) == 0) ws[t >> 5] = ss;
        __syncthreads();
        if (t == 0) {
            float sum = 0.f;
            #pragma unroll
            for (int i = 0; i < 8; i++) sum += ws[i];
            ws[8] = rsqrtf(sum);
        }
        __syncthreads();
        float fa = ws[8] * ASCALE;
        uchar4 p0 = make_uchar4(to_e4m3(x0.x*fa), to_e4m3(x0.y*fa),
                                to_e4m3(x0.z*fa), to_e4m3(x0.w*fa));
        uchar4 p1 = make_uchar4(to_e4m3(x1.x*fa), to_e4m3(x1.y*fa),
                                to_e4m3(x1.z*fa), to_e4m3(x1.w*fa));
        uint32_t* d8 = (uint32_t*)(g_a8 + (size_t)r * FEAT);
        d8[t]       = *reinterpret_cast<uint32_t*>(&p0);
        d8[t + 256] = *reinterpret_cast<uint32_t*>(&p1);
    }
}

// ---------------- mma helpers ----------------
__device__ __forceinline__ void ldmx4(uint32_t* r, uint32_t a) {
    asm volatile("ldmatrix.sync.aligned.m8n8.x4.shared.b16 {%0,%1,%2,%3},[%4];\n"
                 : "=r"(r[0]), "=r"(r[1]), "=r"(r[2]), "=r"(r[3]) : "r"(a));
}
__device__ __forceinline__ void mma16832f8(float* c, const uint32_t* a, const uint32_t* b) {
    asm volatile("mma.sync.aligned.m16n8k32.row.col.f32.e4m3.e4m3.f32 "
                 "{%0,%1,%2,%3},{%4,%5,%6,%7},{%8,%9},{%0,%1,%2,%3};\n"
                 : "+f"(c[0]), "+f"(c[1]), "+f"(c[2]), "+f"(c[3])
                 : "r"(a[0]), "r"(a[1]), "r"(a[2]), "r"(a[3]),
                   "r"(b[0]), "r"(b[1]));
}
__device__ __forceinline__ void cpa16(uint32_t dst, const void* src) {
    asm volatile("cp.async.cg.shared.global [%0], [%1], 16;" :: "r"(dst), "l"(src));
}
__device__ __forceinline__ void cpa_commit() {
    asm volatile("cp.async.commit_group;" ::: "memory");
}
template <int N> __device__ __forceinline__ void cpa_wait() {
    asm volatile("cp.async.wait_group %0;" :: "n"(N) : "memory");
}

// ======================= shared fp8 (MF*64)x64x2048 mainloop =======================
// MF=2: 128-row tile (full). MF=1: 64-row tile (half-duration tail filler).
// R15 structure (converged): eager prefetch right after barrier, in-order ks.
#define F8_BB   8192
#define G1_SMEM (3 * (128 * 128 + F8_BB))   // 73728 (worst case MF=2)
#define G1_NSTG 16

template <int MF>
__device__ __forceinline__ void fp8_mainloop(
    const uint8_t* __restrict__ asrc_base, const uint8_t* __restrict__ bsrc_base,
    uint32_t sb, int tid, int lane, int wm, int wn,
    float* sInv, int inv_base, float c[2][4][4])
{
    constexpr int AB  = MF * 64 * 128;
    constexpr int STG = AB + F8_BB;

    #pragma unroll
    for (int mf = 0; mf < MF; mf++)
        #pragma unroll
        for (int nf = 0; nf < 4; nf++)
            #pragma unroll
            for (int j = 0; j < 4; j++) c[mf][nf][j] = 0.f;

    int arow = tid >> 3, q = tid & 7;
    uint32_t asw = (uint32_t)((q ^ (arow & 7)) << 4);
    uint32_t adst0 = (uint32_t)(arow * 128) + asw;
    const uint8_t* asrc0 = asrc_base + (size_t)arow * FEAT + q * 16;
    uint32_t bdst0 = (uint32_t)AB + (uint32_t)(arow * 128) + asw;
    const uint8_t* bsrc0 = bsrc_base + (size_t)arow * FEAT + q * 16;

    int koff = 0;
    auto issue_stage = [&](uint32_t bufbase) {
        #pragma unroll
        for (int i = 0; i < 2 * MF; i++)
            cpa16(bufbase + adst0 + i * 4096, asrc0 + (size_t)i * 32 * FEAT + koff);
        #pragma unroll
        for (int i = 0; i < 2; i++)
            cpa16(bufbase + bdst0 + i * 4096, bsrc0 + (size_t)i * 32 * FEAT + koff);
        cpa_commit();
        koff += 128;
    };

    int arow0 = wm * (16 * MF) + (lane & 15);
    int brow0 = wn * 32 + (lane & 7) + ((lane >> 4) << 3);
    int ahi = lane >> 4, bhi = (lane >> 3) & 1;
    uint32_t aoff = (uint32_t)(arow0 * 128);
    uint32_t boff = (uint32_t)AB + (uint32_t)(brow0 * 128);
    uint32_t colA[4], colB[4];
    #pragma unroll
    for (int ks = 0; ks < 4; ks++) {
        colA[ks] = (uint32_t)(((ks * 2 + ahi) ^ (arow0 & 7)) << 4);
        colB[ks] = (uint32_t)(((ks * 2 + bhi) ^ (brow0 & 7)) << 4);
    }

    issue_stage(sb);
    issue_stage(sb + STG);

    if (inv_base >= 0 && tid < 64) {     // hidden under pipeline fill
        int cidx = inv_base + tid;
        float s = 0.f;
        #pragma unroll
        for (int i = 0; i < 16; i++) s += g_colsqp[i * NPAD + cidx];
        sInv[tid] = (cidx < NCLS) ? (28.0f / (ASCALE * WSCALE)) * rsqrtf(s) : 0.f;
    }

    for (int kt = 0; kt < G1_NSTG; kt++) {
        uint32_t bufbase = sb + (kt % 3) * STG;
        if (kt < G1_NSTG - 1) cpa_wait<1>(); else cpa_wait<0>();
        __syncthreads();
        if (kt + 2 < G1_NSTG) issue_stage(sb + ((kt + 2) % 3) * STG);

        uint32_t abase = bufbase + aoff;
        uint32_t bbase = bufbase + boff;
        #pragma unroll
        for (int ks = 0; ks < 4; ks++) {
            uint32_t a[2][4], b[4][2];
            #pragma unroll
            for (int mf = 0; mf < MF; mf++)
                ldmx4(a[mf], abase + mf * 2048 + colA[ks]);
            {
                uint32_t r[4];
                ldmx4(r, bbase + colB[ks]);
                b[0][0] = r[0]; b[0][1] = r[1];
                b[1][0] = r[2]; b[1][1] = r[3];
                ldmx4(r, bbase + 2048 + colB[ks]);
                b[2][0] = r[0]; b[2][1] = r[1];
                b[3][0] = r[2]; b[3][1] = r[3];
            }
            #pragma unroll
            for (int mf = 0; mf < MF; mf++)
                #pragma unroll
                for (int nf = 0; nf < 4; nf++)
                    mma16832f8(c[mf][nf], a[mf], b[nf]);
        }
    }
}

// gemm1 epilogue: fixed-max (28) chunkwise sum-exp
template <int MF>
__device__ __forceinline__ void g1_epilogue(int rowbase, int ntile,
                                            float c[2][4][4], const float* sInv,
                                            int lane, int wm, int wn)
{
    int g = lane >> 2, tg = lane & 3;
    #pragma unroll
    for (int mf = 0; mf < MF; mf++)
        #pragma unroll
        for (int pr = 0; pr < 2; pr++) {
            int R = rowbase + wm * (16 * MF) + mf * 16 + pr * 8 + g;
            int lbl = g_lab[R & (BATCH - 1)];
            float s = 0.f;
            #pragma unroll
            for (int nf = 0; nf < 4; nf++)
                #pragma unroll
                for (int j = 0; j < 2; j++) {
                    int nl = wn * 32 + nf * 8 + tg * 2 + j;
                    int n = ntile * 64 + nl;
                    float val = c[mf][nf][pr * 2 + j] * sInv[nl];
                    if (n >= NCLS) val = -1e30f;
                    if (n == lbl) g_ll[R] = val;
                    s += __expf(val - LSE_MAX);
                }
            s += __shfl_xor_sync(0xffffffffu, s, 1);
            s += __shfl_xor_sync(0xffffffffu, s, 2);
            if (tg == 0) {
                int chunk = ntile * 2 + wn;
                g_psum[chunk * ROWS2 + R] = s;
            }
        }
}

// ======================= gemm_fused =======================
// [0, 2536): gemm1 full 128-row tiles   (6 clean waves with gemm2: 2664 = 6*444)
// [2536, 2664): gemm2 128x64 tiles      (same duration as gemm1 fulls)
// [2664, 3096): gemm1 half 64-row tiles (T/2 duration -> packs the tail wave)
__global__ __launch_bounds__(256, 3) void gemm_fused_kernel() {
    extern __shared__ char smem[];
    __shared__ float sInv[64];
    int tid = threadIdx.x, warp = tid >> 5, lane = tid & 31;
    int wm = warp & 3, wn = warp >> 2;
    uint32_t sb = (uint32_t)__cvta_generic_to_shared(smem);
    float c[2][4][4];
    int bid = blockIdx.x;

    if (bid < G1F_BLOCKS) {
        // ---- gemm1 full tile ----
        int mtile = bid / NT1, ntile = bid % NT1;
        fp8_mainloop<2>(g_a8 + (size_t)(mtile * 128) * FEAT,
                        g_w8t + (size_t)(ntile * 64) * FEAT,
                        sb, tid, lane, wm, wn, sInv, ntile * 64, c);
        g1_epilogue<2>(mtile * 128, ntile, c, sInv, lane, wm, wn);
    } else if (bid < G1F_BLOCKS + G2_BLOCKS) {
        // ---- gemm2: fp8 sim + soft-margin ----
        int bid2 = bid - G1F_BLOCKS;            // 0..127
        int ntile2 = bid2 & 15, mtile2 = bid2 >> 4;   // 16 n x 8 m
        fp8_mainloop<2>(g_a8 + (size_t)(mtile2 * 128) * FEAT,
                        g_a8 + (size_t)(BATCH + ntile2 * 64) * FEAT,
                        sb, tid, lane, wm, wn, sInv, -1, c);

        int g = lane >> 2, tg = lane & 3;
        float local = 0.f;
        #pragma unroll
        for (int mf = 0; mf < 2; mf++)
            #pragma unroll
            for (int pr = 0; pr < 2; pr++) {
                int R = mtile2 * 128 + wm * 32 + mf * 16 + pr * 8 + g;
                int lr = g_lab[R];
                #pragma unroll
                for (int nf = 0; nf < 4; nf++)
                    #pragma unroll
                    for (int j = 0; j < 2; j++) {
                        int n = ntile2 * 64 + wn * 32 + nf * 8 + tg * 2 + j;
                        int lc = g_lab[n];
                        float s = c[mf][nf][pr * 2 + j] * DESCALE2;
                        float x = (lr == lc) ? (-10.f * (s - 0.6f))
                                             : (40.f * (s - 0.4f));
                        local += (x > 15.f) ? x : log1pf(__expf(x));
                    }
            }
        #pragma unroll
        for (int o = 16; o > 0; o >>= 1) local += __shfl_xor_sync(0xffffffffu, local, o);
        if (lane == 0) sInv[warp] = local;      // reuse sInv as scratch
        __syncthreads();
        if (tid == 0) {
            float t2 = 0.f;
            #pragma unroll
            for (int i = 0; i < 8; i++) t2 += sInv[i];
            g_gal_part[bid2] = t2;
        }
    } else {
        // ---- gemm1 half tile (64 rows) ----
        int h = bid - (G1F_BLOCKS + G2_BLOCKS);       // 0..431
        int gt = G1F_BLOCKS + (h >> 1);               // global tile 2536..2751
        int mtile = gt / NT1, ntile = gt % NT1;
        int half = h & 1;
        fp8_mainloop<1>(g_a8 + (size_t)(mtile * 128 + half * 64) * FEAT,
                        g_w8t + (size_t)(ntile * 64) * FEAT,
                        sb, tid, lane, wm, wn, sInv, ntile * 64, c);
        g1_epilogue<1>(mtile * 128 + half * 64, ntile, c, sInv, lane, wm, wn);
    }
}

// ---------------- combine + finalize (fixed-max LSE; last-block pattern) ----------------
__global__ void combine_final_kernel(float* __restrict__ out) {
    int r = blockIdx.x * 64 + threadIdx.x;
    float s = 0.f;
    #pragma unroll 8
    for (int i = 0; i < NCH; i++) s += g_psum[i * ROWS2 + r];
    float contrib = LSE_MAX + logf(s) - g_ll[r];

    int lane = threadIdx.x & 31, wid = threadIdx.x >> 5;
    #pragma unroll
    for (int o = 16; o > 0; o >>= 1) contrib += __shfl_xor_sync(0xffffffffu, contrib, o);
    __shared__ float ws[2];
    __shared__ int s_ticket;
    if (lane == 0) ws[wid] = contrib;
    __syncthreads();
    if (threadIdx.x == 0) {
        g_inst_part[blockIdx.x] = ws[0] + ws[1];
        __threadfence();
        s_ticket = atomicAdd(&g_ctr, 1);
    }
    __syncthreads();
    if (s_ticket == 31) {
        if (threadIdx.x == 0) {
            float si = 0.f;
            for (int i = 0; i < 32; i++) si += g_inst_part[i];
            float sg = 0.f;
            for (int i = 0; i < G2_BLOCKS; i++) sg += g_gal_part[i];
            out[0] = si * (1.0f / BATCH);
            out[1] = 2.0f * sg / BATCH;
            g_ctr = 0;                   // reset for next graph replay
        }
    }
}

// ---------------- launch: 3 kernels, one stream ----------------
extern "C" void kernel_launch(void* const* d_in, const int* in_sizes, int n_in,
                              void* d_out, int out_size) {
    const float* vis = (const float*)d_in[0];
    const float* txt = (const float*)d_in[1];
    const int* lab = (const int*)d_in[2];
    const float* W = (const float*)d_in[3];
    float* out = (float*)d_out;

    cudaFuncSetAttribute(gemm_fused_kernel,
                         cudaFuncAttributeMaxDynamicSharedMemorySize, G1_SMEM);

    prep_fused_kernel<<<WT_BLOCKS + ROWS2, 256>>>(W, vis, txt, lab);
    gemm_fused_kernel<<<TOT_BLOCKS, 256, G1_SMEM>>>();
    combine_final_kernel<<<32, 64>>>(out);
}